// round 2
// baseline (speedup 1.0000x reference)
#include <cuda_runtime.h>
#include <stdint.h>
#include <math.h>

// Problem dims (fixed by setup_inputs)
#define NB    512          // batch
#define NIN   3072         // input size (3*32*32)
#define NHID  2048         // hidden
#define NOUT  512          // output
#define NSTEP 10           // T
#define NTOT  (NB * NIN)   // 1572864 uniform draws per step

// ---------------- scratch state (static device globals; no allocs) ---------
__device__ float g_p  [NB * NIN];    // sigmoid(x)
__device__ float g_pre[NB * NIN];    // input spikes (0/1) for current step
__device__ float g_v  [NB * NHID];   // LIF membrane potential
__device__ float g_spk[NB * NHID];   // hidden spikes (0/1) for current step
__device__ unsigned int g_keys[2 * NSTEP];  // per-step (k1, k2) from split()

// ---------------- Threefry-2x32, exactly matching JAX ---------------------
__device__ __forceinline__ void tf2x32(unsigned int k0, unsigned int k1,
                                       unsigned int& x0, unsigned int& x1) {
    unsigned int ks2 = k0 ^ k1 ^ 0x1BD11BDAu;
    x0 += k0; x1 += k1;
#define TF_RND(r) { x0 += x1; x1 = (x1 << (r)) | (x1 >> (32 - (r))); x1 ^= x0; }
    TF_RND(13) TF_RND(15) TF_RND(26) TF_RND(6)
    x0 += k1;  x1 += ks2 + 1u;
    TF_RND(17) TF_RND(29) TF_RND(16) TF_RND(24)
    x0 += ks2; x1 += k0 + 2u;
    TF_RND(13) TF_RND(15) TF_RND(26) TF_RND(6)
    x0 += k0;  x1 += k1 + 3u;
    TF_RND(17) TF_RND(29) TF_RND(16) TF_RND(24)
    x0 += k1;  x1 += ks2 + 4u;
    TF_RND(13) TF_RND(15) TF_RND(26) TF_RND(6)
    x0 += ks2; x1 += k0 + 5u;
#undef TF_RND
}

// ---------------- init: sigmoid(x), zero v / s, per-step keys -------------
// Partitionable threefry split: counts = 64-bit iota over (10,),
// (hi, lo) = (0, t); key_t = (lane0, lane1) of TF(key, (0, t)).
__global__ void init_kernel(const float* __restrict__ x, float* __restrict__ s_out) {
    int m = blockIdx.x * blockDim.x + threadIdx.x;
    if (m < NB * NIN) {
        // XLA logistic expansion: 1/(1+exp(-x)) in f32, exp correctly rounded
        float xv = x[m];
        float ef = (float)exp((double)(-xv));        // == correctly-rounded expf
        g_p[m] = __fdiv_rn(1.0f, __fadd_rn(1.0f, ef));
    }
    if (m < NB * NHID) g_v[m] = 0.0f;
    if (m < NB * NOUT) s_out[m] = 0.0f;
    if (m < NSTEP) {
        unsigned int x0 = 0u, x1 = (unsigned)m;
        tf2x32(0u, 42u, x0, x1);                     // key = (0, 42)
        g_keys[2 * m]     = x0;
        g_keys[2 * m + 1] = x1;
    }
}

// ---------------- per-step input spike generation -------------------------
// Partitionable random_bits: per element m, (b0,b1) = TF(key_t, (m>>32, m));
// 32-bit output = b0 ^ b1. size < 2^32 so hi counter = 0.
__global__ void spike_kernel(int t) {
    int m = blockIdx.x * blockDim.x + threadIdx.x;
    if (m >= NTOT) return;
    unsigned int k0 = g_keys[2 * t];
    unsigned int k1 = g_keys[2 * t + 1];
    unsigned int x0 = 0u;
    unsigned int x1 = (unsigned)m;
    tf2x32(k0, k1, x0, x1);
    unsigned int bits = x0 ^ x1;
    float u = __uint_as_float((bits >> 9) | 0x3f800000u) - 1.0f;
    g_pre[m] = (u < g_p[m]) ? 1.0f : 0.0f;
}

// ---------------- GEMM1: h = pre @ W_in^T, fused LIF update ---------------
// A = g_pre [NB, NIN] row-major, B = W_in [NHID, NIN] row-major (NT gemm)
// tile 64x64, BK=32, 256 threads, each thread 4x4
__global__ void gemm_lif(const float* __restrict__ Win) {
    __shared__ float As[32][65];
    __shared__ float Bs[32][65];
    const int bm = blockIdx.y * 64;   // batch rows
    const int bn = blockIdx.x * 64;   // hidden cols
    const int tid = threadIdx.x;
    const int tx = tid % 16, ty = tid / 16;

    float acc[4][4] = {};
    for (int k0 = 0; k0 < NIN; k0 += 32) {
#pragma unroll
        for (int e = tid; e < 64 * 32; e += 256) {
            int r = e / 32, c = e % 32;   // coalesced over c
            As[c][r] = g_pre[(bm + r) * NIN + k0 + c];
            Bs[c][r] = Win  [(bn + r) * NIN + k0 + c];
        }
        __syncthreads();
#pragma unroll
        for (int k = 0; k < 32; k++) {
            float a[4], b[4];
#pragma unroll
            for (int i = 0; i < 4; i++) { a[i] = As[k][ty * 4 + i]; b[i] = Bs[k][tx * 4 + i]; }
#pragma unroll
            for (int i = 0; i < 4; i++)
#pragma unroll
                for (int j = 0; j < 4; j++)
                    acc[i][j] = fmaf(a[i], b[j], acc[i][j]);
        }
        __syncthreads();
    }
    // LIF epilogue: v = v*DECAY + h; spike = v>=1; v = spike?0:v
#pragma unroll
    for (int i = 0; i < 4; i++) {
        int row = bm + ty * 4 + i;
#pragma unroll
        for (int j = 0; j < 4; j++) {
            int col = bn + tx * 4 + j;
            int idx = row * NHID + col;
            float vv = g_v[idx];
            // keep mul and add separate (no FMA contraction) to mirror XLA
            float vn = __fadd_rn(__fmul_rn(vv, 0.3f), acc[i][j]);
            float sp = (vn >= 1.0f) ? 1.0f : 0.0f;
            g_v[idx]   = (vn >= 1.0f) ? 0.0f : vn;
            g_spk[idx] = sp;
        }
    }
}

// ---------------- GEMM2: out = spk @ W_out^T + b_out; s += (out > 0) ------
// tile 32x32, BK=32, 64 threads, each thread 4x4 -> grid 16x16 = 256 blocks
__global__ void gemm_out(const float* __restrict__ Wout,
                         const float* __restrict__ bout,
                         float* __restrict__ s) {
    __shared__ float As[32][33];
    __shared__ float Bs[32][33];
    const int bm = blockIdx.y * 32;   // batch rows
    const int bn = blockIdx.x * 32;   // output cols
    const int tid = threadIdx.x;
    const int tx = tid % 8, ty = tid / 8;

    float acc[4][4] = {};
    for (int k0 = 0; k0 < NHID; k0 += 32) {
#pragma unroll
        for (int e = tid; e < 32 * 32; e += 64) {
            int r = e / 32, c = e % 32;
            As[c][r] = g_spk[(bm + r) * NHID + k0 + c];
            Bs[c][r] = Wout [(bn + r) * NHID + k0 + c];
        }
        __syncthreads();
#pragma unroll
        for (int k = 0; k < 32; k++) {
            float a[4], b[4];
#pragma unroll
            for (int i = 0; i < 4; i++) { a[i] = As[k][ty * 4 + i]; b[i] = Bs[k][tx * 4 + i]; }
#pragma unroll
            for (int i = 0; i < 4; i++)
#pragma unroll
                for (int j = 0; j < 4; j++)
                    acc[i][j] = fmaf(a[i], b[j], acc[i][j]);
        }
        __syncthreads();
    }
#pragma unroll
    for (int i = 0; i < 4; i++) {
        int row = bm + ty * 4 + i;
#pragma unroll
        for (int j = 0; j < 4; j++) {
            int col = bn + tx * 4 + j;
            float o = __fadd_rn(acc[i][j], bout[col]);
            if (o > 0.0f) {
                int idx = row * NOUT + col;
                s[idx] = s[idx] + 1.0f;
            }
        }
    }
}

// ---------------- launch ---------------------------------------------------
extern "C" void kernel_launch(void* const* d_in, const int* in_sizes, int n_in,
                              void* d_out, int out_size) {
    const float* x    = (const float*)d_in[0];
    const float* Win  = (const float*)d_in[1];
    const float* Wout = (const float*)d_in[2];
    const float* bout = (const float*)d_in[3];
    float* s = (float*)d_out;

    init_kernel<<<(NB * NIN + 255) / 256, 256>>>(x, s);
    for (int t = 0; t < NSTEP; t++) {
        spike_kernel<<<(NTOT + 255) / 256, 256>>>(t);
        gemm_lif<<<dim3(NHID / 64, NB / 64), 256>>>(Win);
        gemm_out<<<dim3(NOUT / 32, NB / 32), 64>>>(Wout, bout, s);
    }
}

// round 4
// speedup vs baseline: 1.4430x; 1.4430x over previous
#include <cuda_runtime.h>
#include <stdint.h>
#include <math.h>

// Problem dims (fixed by setup_inputs)
#define NB    512
#define NIN   3072
#define NHID  2048
#define NOUT  512
#define NSTEP 10
#define NTOT  (NB * NIN)

// ---------------- scratch state (static device globals; no allocs) ---------
__device__ float g_p  [NTOT];        // sigmoid(x)
__device__ float g_pre[NTOT];        // input spikes (0/1) for current step
__device__ float g_v  [NB * NHID];   // LIF membrane potential
__device__ float g_spk[NB * NHID];   // hidden spikes (0/1) for current step
__device__ unsigned int g_keys[2 * NSTEP];  // per-step keys from split()

// ---------------- Threefry-2x32 (partitionable), matching JAX -------------
__device__ __forceinline__ void tf2x32(unsigned int k0, unsigned int k1,
                                       unsigned int& x0, unsigned int& x1) {
    unsigned int ks2 = k0 ^ k1 ^ 0x1BD11BDAu;
    x0 += k0; x1 += k1;
#define TF_RND(r) { x0 += x1; x1 = (x1 << (r)) | (x1 >> (32 - (r))); x1 ^= x0; }
    TF_RND(13) TF_RND(15) TF_RND(26) TF_RND(6)
    x0 += k1;  x1 += ks2 + 1u;
    TF_RND(17) TF_RND(29) TF_RND(16) TF_RND(24)
    x0 += ks2; x1 += k0 + 2u;
    TF_RND(13) TF_RND(15) TF_RND(26) TF_RND(6)
    x0 += k0;  x1 += k1 + 3u;
    TF_RND(17) TF_RND(29) TF_RND(16) TF_RND(24)
    x0 += k1;  x1 += ks2 + 4u;
    TF_RND(13) TF_RND(15) TF_RND(26) TF_RND(6)
    x0 += ks2; x1 += k0 + 5u;
#undef TF_RND
}

// ---------------- init: sigmoid, zero v/s, per-step keys ------------------
__global__ void init_kernel(const float* __restrict__ x, float* __restrict__ s_out) {
    int m = blockIdx.x * blockDim.x + threadIdx.x;
    if (m < NTOT) {
        float xv = x[m];
        float ef = (float)exp((double)(-xv));        // correctly-rounded expf
        g_p[m] = __fdiv_rn(1.0f, __fadd_rn(1.0f, ef));
    }
    if (m < NB * NHID) g_v[m] = 0.0f;
    if (m < NB * NOUT) s_out[m] = 0.0f;
    if (m < NSTEP) {
        unsigned int x0 = 0u, x1 = (unsigned)m;
        tf2x32(0u, 42u, x0, x1);                     // key = (0, 42)
        g_keys[2 * m] = x0; g_keys[2 * m + 1] = x1;
    }
}

// ---------------- per-step input spikes (partitionable random_bits) -------
__global__ void spike_kernel(int t) {
    int m = blockIdx.x * blockDim.x + threadIdx.x;
    if (m >= NTOT) return;
    unsigned int x0 = 0u, x1 = (unsigned)m;
    tf2x32(g_keys[2 * t], g_keys[2 * t + 1], x0, x1);
    unsigned int bits = x0 ^ x1;
    float u = __uint_as_float((bits >> 9) | 0x3f800000u) - 1.0f;
    g_pre[m] = (u < g_p[m]) ? 1.0f : 0.0f;
}

// ---------------- GEMM1: h = pre @ W_in^T, fused LIF update ---------------
// (identical to the R2 bit-exact version: 64x64 tile, BK=32, 256t, 4x4)
__global__ void gemm_lif(const float* __restrict__ Win) {
    __shared__ float As[32][65];
    __shared__ float Bs[32][65];
    const int bm = blockIdx.y * 64;   // batch rows
    const int bn = blockIdx.x * 64;   // hidden cols
    const int tid = threadIdx.x;
    const int tx = tid % 16, ty = tid / 16;

    float acc[4][4] = {};
    for (int k0 = 0; k0 < NIN; k0 += 32) {
#pragma unroll
        for (int e = tid; e < 64 * 32; e += 256) {
            int r = e / 32, c = e % 32;
            As[c][r] = g_pre[(bm + r) * NIN + k0 + c];
            Bs[c][r] = Win  [(bn + r) * NIN + k0 + c];
        }
        __syncthreads();
#pragma unroll
        for (int k = 0; k < 32; k++) {
            float a[4], b[4];
#pragma unroll
            for (int i = 0; i < 4; i++) { a[i] = As[k][ty * 4 + i]; b[i] = Bs[k][tx * 4 + i]; }
#pragma unroll
            for (int i = 0; i < 4; i++)
#pragma unroll
                for (int j = 0; j < 4; j++)
                    acc[i][j] = fmaf(a[i], b[j], acc[i][j]);
        }
        __syncthreads();
    }
    // LIF epilogue: v = v*DECAY + h; spike = v>=1; reset
#pragma unroll
    for (int i = 0; i < 4; i++) {
        int row = bm + ty * 4 + i;
#pragma unroll
        for (int j = 0; j < 4; j++) {
            int col = bn + tx * 4 + j;
            int idx = row * NHID + col;
            float vv = g_v[idx];
            float vn = __fadd_rn(__fmul_rn(vv, 0.3f), acc[i][j]);
            float sp = (vn >= 1.0f) ? 1.0f : 0.0f;
            g_v[idx]   = (vn >= 1.0f) ? 0.0f : vn;
            g_spk[idx] = sp;
        }
    }
}

// ---------------- GEMM2: out = spk @ W_out^T + b_out; s += (out > 0) ------
// Retiled for occupancy: 32(m) x 64(n) tile, BK=32, 256 threads, 2x4/thread.
// Per-output arithmetic chain (ascending-k fmaf, BK=32) is bit-identical to
// the R2 version -- only the M/N work distribution changed.
__global__ void gemm_out(const float* __restrict__ Wout,
                         const float* __restrict__ bout,
                         float* __restrict__ s) {
    __shared__ float As[32][34];      // [k][m], float2-aligned rows
    __shared__ float Bs[32][68];      // [k][n], float4-aligned rows
    const int bm = blockIdx.y * 32;   // batch rows
    const int bn = blockIdx.x * 64;   // output cols
    const int tid = threadIdx.x;
    const int tx = tid % 16, ty = tid / 16;   // tx -> n (x4), ty -> m (x2)

    float acc[2][4] = {};
    for (int k0 = 0; k0 < NHID; k0 += 32) {
#pragma unroll
        for (int e = tid; e < 32 * 32; e += 256) {   // A: 4 per thread
            int r = e / 32, c = e % 32;
            As[c][r] = g_spk[(bm + r) * NHID + k0 + c];
        }
#pragma unroll
        for (int e = tid; e < 64 * 32; e += 256) {   // B: 8 per thread
            int r = e / 32, c = e % 32;
            Bs[c][r] = Wout[(bn + r) * NHID + k0 + c];
        }
        __syncthreads();
#pragma unroll
        for (int k = 0; k < 32; k++) {
            float2 a = *(const float2*)&As[k][ty * 2];
            float4 b = *(const float4*)&Bs[k][tx * 4];
            float av[2] = {a.x, a.y};
            float bv[4] = {b.x, b.y, b.z, b.w};
#pragma unroll
            for (int i = 0; i < 2; i++)
#pragma unroll
                for (int j = 0; j < 4; j++)
                    acc[i][j] = fmaf(av[i], bv[j], acc[i][j]);
        }
        __syncthreads();
    }
#pragma unroll
    for (int i = 0; i < 2; i++) {
        int row = bm + ty * 2 + i;
#pragma unroll
        for (int j = 0; j < 4; j++) {
            int col = bn + tx * 4 + j;
            float o = __fadd_rn(acc[i][j], bout[col]);
            if (o > 0.0f) {
                int idx = row * NOUT + col;
                s[idx] = s[idx] + 1.0f;
            }
        }
    }
}

// ---------------- launch ---------------------------------------------------
extern "C" void kernel_launch(void* const* d_in, const int* in_sizes, int n_in,
                              void* d_out, int out_size) {
    const float* x    = (const float*)d_in[0];
    const float* Win  = (const float*)d_in[1];
    const float* Wout = (const float*)d_in[2];
    const float* bout = (const float*)d_in[3];
    float* s = (float*)d_out;

    init_kernel<<<(NTOT + 255) / 256, 256>>>(x, s);
    for (int t = 0; t < NSTEP; t++) {
        spike_kernel<<<(NTOT + 255) / 256, 256>>>(t);
        gemm_lif<<<dim3(NHID / 64, NB / 64), 256>>>(Win);
        gemm_out<<<dim3(NOUT / 64, NB / 32), 256>>>(Wout, bout, s);
    }
}

// round 5
// speedup vs baseline: 1.8546x; 1.2853x over previous
#include <cuda_runtime.h>
#include <stdint.h>
#include <math.h>

// Problem dims (fixed by setup_inputs)
#define NB    512
#define NIN   3072
#define NHID  2048
#define NOUT  512
#define NSTEP 10
#define NTOT  (NB * NIN)

// ---------------- scratch state (static device globals; no allocs) ---------
__device__ float g_p  [NTOT];        // sigmoid(x)
__device__ float g_pre[NTOT];        // input spikes (0/1) for current step
__device__ float g_v  [NB * NHID];   // LIF membrane potential
__device__ float g_spk[NB * NHID];   // hidden spikes (0/1) for current step
__device__ unsigned int g_keys[2 * NSTEP];  // per-step keys from split()
__device__ float g_Wt [NHID * NOUT]; // W_out^T  [k][n], built once per launch
__device__ int   g_idx[NB * NHID];   // per-row ascending nonzero-spike indices
__device__ int   g_nnz[NB];          // per-row nonzero count

// ---------------- Threefry-2x32 (partitionable), matching JAX -------------
__device__ __forceinline__ void tf2x32(unsigned int k0, unsigned int k1,
                                       unsigned int& x0, unsigned int& x1) {
    unsigned int ks2 = k0 ^ k1 ^ 0x1BD11BDAu;
    x0 += k0; x1 += k1;
#define TF_RND(r) { x0 += x1; x1 = (x1 << (r)) | (x1 >> (32 - (r))); x1 ^= x0; }
    TF_RND(13) TF_RND(15) TF_RND(26) TF_RND(6)
    x0 += k1;  x1 += ks2 + 1u;
    TF_RND(17) TF_RND(29) TF_RND(16) TF_RND(24)
    x0 += ks2; x1 += k0 + 2u;
    TF_RND(13) TF_RND(15) TF_RND(26) TF_RND(6)
    x0 += k0;  x1 += k1 + 3u;
    TF_RND(17) TF_RND(29) TF_RND(16) TF_RND(24)
    x0 += k1;  x1 += ks2 + 4u;
    TF_RND(13) TF_RND(15) TF_RND(26) TF_RND(6)
    x0 += ks2; x1 += k0 + 5u;
#undef TF_RND
}

// ---------------- init: sigmoid, zero v/s, per-step keys ------------------
__global__ void init_kernel(const float* __restrict__ x, float* __restrict__ s_out) {
    int m = blockIdx.x * blockDim.x + threadIdx.x;
    if (m < NTOT) {
        float xv = x[m];
        float ef = (float)exp((double)(-xv));        // correctly-rounded expf
        g_p[m] = __fdiv_rn(1.0f, __fadd_rn(1.0f, ef));
    }
    if (m < NB * NHID) g_v[m] = 0.0f;
    if (m < NB * NOUT) s_out[m] = 0.0f;
    if (m < NSTEP) {
        unsigned int x0 = 0u, x1 = (unsigned)m;
        tf2x32(0u, 42u, x0, x1);                     // key = (0, 42)
        g_keys[2 * m] = x0; g_keys[2 * m + 1] = x1;
    }
}

// ---------------- one-time: Wt[k][n] = W_out[n][k] ------------------------
__global__ void transpose_wout(const float* __restrict__ Wout) {
    __shared__ float t[32][33];
    int kb = blockIdx.x * 32, nb = blockIdx.y * 32;
    int tx = threadIdx.x % 32, ty = threadIdx.x / 32;   // 256 threads: 32 x 8
#pragma unroll
    for (int j = 0; j < 32; j += 8)
        t[ty + j][tx] = Wout[(nb + ty + j) * NHID + kb + tx];
    __syncthreads();
#pragma unroll
    for (int j = 0; j < 32; j += 8)
        g_Wt[(kb + ty + j) * NOUT + nb + tx] = t[tx][ty + j];
}

// ---------------- per-step input spikes (partitionable random_bits) -------
__global__ void spike_kernel(int t) {
    int m = blockIdx.x * blockDim.x + threadIdx.x;
    if (m >= NTOT) return;
    unsigned int x0 = 0u, x1 = (unsigned)m;
    tf2x32(g_keys[2 * t], g_keys[2 * t + 1], x0, x1);
    unsigned int bits = x0 ^ x1;
    float u = __uint_as_float((bits >> 9) | 0x3f800000u) - 1.0f;
    g_pre[m] = (u < g_p[m]) ? 1.0f : 0.0f;
}

// ---------------- GEMM1: h = pre @ W_in^T, fused LIF update ---------------
// (bit-exact reference version: 64x64 tile, BK=32, 256t, 4x4 -- unchanged)
__global__ void gemm_lif(const float* __restrict__ Win) {
    __shared__ float As[32][65];
    __shared__ float Bs[32][65];
    const int bm = blockIdx.y * 64;
    const int bn = blockIdx.x * 64;
    const int tid = threadIdx.x;
    const int tx = tid % 16, ty = tid / 16;

    float acc[4][4] = {};
    for (int k0 = 0; k0 < NIN; k0 += 32) {
#pragma unroll
        for (int e = tid; e < 64 * 32; e += 256) {
            int r = e / 32, c = e % 32;
            As[c][r] = g_pre[(bm + r) * NIN + k0 + c];
            Bs[c][r] = Win  [(bn + r) * NIN + k0 + c];
        }
        __syncthreads();
#pragma unroll
        for (int k = 0; k < 32; k++) {
            float a[4], b[4];
#pragma unroll
            for (int i = 0; i < 4; i++) { a[i] = As[k][ty * 4 + i]; b[i] = Bs[k][tx * 4 + i]; }
#pragma unroll
            for (int i = 0; i < 4; i++)
#pragma unroll
                for (int j = 0; j < 4; j++)
                    acc[i][j] = fmaf(a[i], b[j], acc[i][j]);
        }
        __syncthreads();
    }
#pragma unroll
    for (int i = 0; i < 4; i++) {
        int row = bm + ty * 4 + i;
#pragma unroll
        for (int j = 0; j < 4; j++) {
            int col = bn + tx * 4 + j;
            int idx = row * NHID + col;
            float vv = g_v[idx];
            float vn = __fadd_rn(__fmul_rn(vv, 0.3f), acc[i][j]);
            float sp = (vn >= 1.0f) ? 1.0f : 0.0f;
            g_v[idx]   = (vn >= 1.0f) ? 0.0f : vn;
            g_spk[idx] = sp;
        }
    }
}

// ---------------- pack: per-row ascending indices of nonzero spikes -------
// one warp per row; ballot+popc keeps ascending order
__global__ void pack_kernel(void) {
    int wid  = threadIdx.x / 32;
    int lane = threadIdx.x % 32;
    int m = blockIdx.x * 8 + wid;
    if (m >= NB) return;
    int base = 0;
    for (int c = 0; c < NHID; c += 32) {
        float v = g_spk[m * NHID + c + lane];
        unsigned mask = __ballot_sync(0xFFFFFFFFu, v > 0.5f);
        if (v > 0.5f) {
            int rank = __popc(mask & ((1u << lane) - 1u));
            g_idx[m * NHID + base + rank] = c + lane;
        }
        base += __popc(mask);
    }
    if (lane == 0) g_nnz[m] = base;
}

// ---------------- sparse GEMM2: out[m,:] = sum_{k in nnz(m)} Wt[k,:] + b --
// Bit-exact vs dense ascending-k fmaf chain:
//   fmaf(0,w,acc)==acc, fmaf(1,w,acc)==__fadd_rn(acc,w), order preserved.
// block = one row m, 128 threads x 4 contiguous cols (float4 loads of Wt row)
__global__ void gemm_out_sparse(const float* __restrict__ bout,
                                float* __restrict__ s) {
    __shared__ int sidx[128];
    const int m   = blockIdx.x;
    const int tid = threadIdx.x;
    const int n0  = tid * 4;
    const int nnz = g_nnz[m];
    const int* __restrict__ idx = g_idx + m * NHID;

    float a0 = 0.0f, a1 = 0.0f, a2 = 0.0f, a3 = 0.0f;
    for (int c = 0; c < nnz; c += 128) {
        int cn = nnz - c; if (cn > 128) cn = 128;
        if (tid < cn) sidx[tid] = idx[c + tid];
        __syncthreads();
#pragma unroll 4
        for (int i = 0; i < cn; i++) {
            int k = sidx[i];
            float4 w = *(const float4*)&g_Wt[k * NOUT + n0];
            a0 = __fadd_rn(a0, w.x);
            a1 = __fadd_rn(a1, w.y);
            a2 = __fadd_rn(a2, w.z);
            a3 = __fadd_rn(a3, w.w);
        }
        __syncthreads();
    }
    float acc[4] = {a0, a1, a2, a3};
#pragma unroll
    for (int j = 0; j < 4; j++) {
        float o = __fadd_rn(acc[j], bout[n0 + j]);
        if (o > 0.0f) {
            int oi = m * NOUT + n0 + j;
            s[oi] = s[oi] + 1.0f;
        }
    }
}

// ---------------- launch ---------------------------------------------------
extern "C" void kernel_launch(void* const* d_in, const int* in_sizes, int n_in,
                              void* d_out, int out_size) {
    const float* x    = (const float*)d_in[0];
    const float* Win  = (const float*)d_in[1];
    const float* Wout = (const float*)d_in[2];
    const float* bout = (const float*)d_in[3];
    float* s = (float*)d_out;

    init_kernel<<<(NTOT + 255) / 256, 256>>>(x, s);
    transpose_wout<<<dim3(NHID / 32, NOUT / 32), 256>>>(Wout);
    for (int t = 0; t < NSTEP; t++) {
        spike_kernel<<<(NTOT + 255) / 256, 256>>>(t);
        gemm_lif<<<dim3(NHID / 64, NB / 64), 256>>>(Win);
        pack_kernel<<<NB / 8, 256>>>();
        gemm_out_sparse<<<NB, 128>>>(bout, s);
    }
}

// round 6
// speedup vs baseline: 2.0343x; 1.0969x over previous
#include <cuda_runtime.h>
#include <stdint.h>
#include <math.h>

// Problem dims (fixed by setup_inputs)
#define NB    512
#define NIN   3072
#define NHID  2048
#define NOUT  512
#define NSTEP 10
#define NTOT  (NB * NIN)

// ---------------- scratch state (static device globals; no allocs) ---------
__device__ float g_p  [NTOT];        // sigmoid(x)
__device__ float g_pre[NTOT];        // input spikes (0/1) for current step
__device__ float g_v  [NB * NHID];   // LIF membrane potential
__device__ float g_spk[NB * NHID];   // hidden spikes (0/1) for current step
__device__ unsigned int g_keys[2 * NSTEP];  // per-step keys from split()
__device__ float g_Wt [NHID * NOUT]; // W_out^T  [k][n], built once per launch
__device__ int   g_idx[NB * NHID];   // per-row ascending nonzero-spike indices
__device__ int   g_nnz[NB];          // per-row nonzero count

// ---------------- Threefry-2x32 (partitionable), matching JAX -------------
__device__ __forceinline__ void tf2x32(unsigned int k0, unsigned int k1,
                                       unsigned int& x0, unsigned int& x1) {
    unsigned int ks2 = k0 ^ k1 ^ 0x1BD11BDAu;
    x0 += k0; x1 += k1;
#define TF_RND(r) { x0 += x1; x1 = (x1 << (r)) | (x1 >> (32 - (r))); x1 ^= x0; }
    TF_RND(13) TF_RND(15) TF_RND(26) TF_RND(6)
    x0 += k1;  x1 += ks2 + 1u;
    TF_RND(17) TF_RND(29) TF_RND(16) TF_RND(24)
    x0 += ks2; x1 += k0 + 2u;
    TF_RND(13) TF_RND(15) TF_RND(26) TF_RND(6)
    x0 += k0;  x1 += k1 + 3u;
    TF_RND(17) TF_RND(29) TF_RND(16) TF_RND(24)
    x0 += k1;  x1 += ks2 + 4u;
    TF_RND(13) TF_RND(15) TF_RND(26) TF_RND(6)
    x0 += ks2; x1 += k0 + 5u;
#undef TF_RND
}

// ---------------- init: sigmoid, zero v/s, per-step keys ------------------
__global__ void init_kernel(const float* __restrict__ x, float* __restrict__ s_out) {
    int m = blockIdx.x * blockDim.x + threadIdx.x;
    if (m < NTOT) {
        float xv = x[m];
        float ef = (float)exp((double)(-xv));        // correctly-rounded expf
        g_p[m] = __fdiv_rn(1.0f, __fadd_rn(1.0f, ef));
    }
    if (m < NB * NHID) g_v[m] = 0.0f;
    if (m < NB * NOUT) s_out[m] = 0.0f;
    if (m < NSTEP) {
        unsigned int x0 = 0u, x1 = (unsigned)m;
        tf2x32(0u, 42u, x0, x1);                     // key = (0, 42)
        g_keys[2 * m] = x0; g_keys[2 * m + 1] = x1;
    }
}

// ---------------- one-time: Wt[k][n] = W_out[n][k] ------------------------
__global__ void transpose_wout(const float* __restrict__ Wout) {
    __shared__ float t[32][33];
    int kb = blockIdx.x * 32, nb = blockIdx.y * 32;
    int tx = threadIdx.x % 32, ty = threadIdx.x / 32;   // 256 threads: 32 x 8
#pragma unroll
    for (int j = 0; j < 32; j += 8)
        t[ty + j][tx] = Wout[(nb + ty + j) * NHID + kb + tx];
    __syncthreads();
#pragma unroll
    for (int j = 0; j < 32; j += 8)
        g_Wt[(kb + ty + j) * NOUT + nb + tx] = t[tx][ty + j];
}

// ---------------- per-step input spikes (partitionable random_bits) -------
__global__ void spike_kernel(int t) {
    int m = blockIdx.x * blockDim.x + threadIdx.x;
    if (m >= NTOT) return;
    unsigned int x0 = 0u, x1 = (unsigned)m;
    tf2x32(g_keys[2 * t], g_keys[2 * t + 1], x0, x1);
    unsigned int bits = x0 ^ x1;
    float u = __uint_as_float((bits >> 9) | 0x3f800000u) - 1.0f;
    g_pre[m] = (u < g_p[m]) ? 1.0f : 0.0f;
}

// ---------------- GEMM1: h = pre @ W_in^T, fused LIF update ---------------
// 64x64 tile, BK=32, 256 threads, 4x4/thread. Same ascending-k fmaf chain
// as before (bit-exact); data movement vectorized: float4 gmem loads,
// float4 smem compute loads ([32][68] padding keeps 16B alignment).
__global__ void __launch_bounds__(256) gemm_lif(const float* __restrict__ Win) {
    __shared__ float As[32][68];
    __shared__ float Bs[32][68];
    const int bm = blockIdx.y * 64;   // batch rows
    const int bn = blockIdx.x * 64;   // hidden cols
    const int tid = threadIdx.x;
    const int tx = tid % 16, ty = tid / 16;

    float acc[4][4] = {};
    for (int k0 = 0; k0 < NIN; k0 += 32) {
        // load A (64x32) and B (64x32): 2 float4 per thread per matrix
#pragma unroll
        for (int j = 0; j < 2; ++j) {
            int f  = tid * 2 + j;          // 0..511
            int r  = f / 8;                // row 0..63
            int c4 = f % 8;                // float4 within the 32-k row
            float4 av = *(const float4*)&g_pre[(bm + r) * NIN + k0 + c4 * 4];
            float4 bv = *(const float4*)&Win [(bn + r) * NIN + k0 + c4 * 4];
            As[c4 * 4 + 0][r] = av.x; As[c4 * 4 + 1][r] = av.y;
            As[c4 * 4 + 2][r] = av.z; As[c4 * 4 + 3][r] = av.w;
            Bs[c4 * 4 + 0][r] = bv.x; Bs[c4 * 4 + 1][r] = bv.y;
            Bs[c4 * 4 + 2][r] = bv.z; Bs[c4 * 4 + 3][r] = bv.w;
        }
        __syncthreads();
#pragma unroll
        for (int k = 0; k < 32; k++) {
            float4 a4 = *(const float4*)&As[k][ty * 4];
            float4 b4 = *(const float4*)&Bs[k][tx * 4];
            float a[4] = {a4.x, a4.y, a4.z, a4.w};
            float b[4] = {b4.x, b4.y, b4.z, b4.w};
#pragma unroll
            for (int i = 0; i < 4; i++)
#pragma unroll
                for (int j = 0; j < 4; j++)
                    acc[i][j] = fmaf(a[i], b[j], acc[i][j]);
        }
        __syncthreads();
    }
    // LIF epilogue (unchanged, bit-exact)
#pragma unroll
    for (int i = 0; i < 4; i++) {
        int row = bm + ty * 4 + i;
#pragma unroll
        for (int j = 0; j < 4; j++) {
            int col = bn + tx * 4 + j;
            int idx = row * NHID + col;
            float vv = g_v[idx];
            float vn = __fadd_rn(__fmul_rn(vv, 0.3f), acc[i][j]);
            float sp = (vn >= 1.0f) ? 1.0f : 0.0f;
            g_v[idx]   = (vn >= 1.0f) ? 0.0f : vn;
            g_spk[idx] = sp;
        }
    }
}

// ---------------- pack: per-row ascending indices of nonzero spikes -------
__global__ void pack_kernel(void) {
    int wid  = threadIdx.x / 32;
    int lane = threadIdx.x % 32;
    int m = blockIdx.x * 8 + wid;
    if (m >= NB) return;
    int base = 0;
    for (int c = 0; c < NHID; c += 32) {
        float v = g_spk[m * NHID + c + lane];
        unsigned mask = __ballot_sync(0xFFFFFFFFu, v > 0.5f);
        if (v > 0.5f) {
            int rank = __popc(mask & ((1u << lane) - 1u));
            g_idx[m * NHID + base + rank] = c + lane;
        }
        base += __popc(mask);
    }
    if (lane == 0) g_nnz[m] = base;
}

// ---------------- sparse GEMM2: out[m,:] = sum_{k in nnz(m)} Wt[k,:] + b --
__global__ void gemm_out_sparse(const float* __restrict__ bout,
                                float* __restrict__ s) {
    __shared__ int sidx[128];
    const int m   = blockIdx.x;
    const int tid = threadIdx.x;
    const int n0  = tid * 4;
    const int nnz = g_nnz[m];
    const int* __restrict__ idx = g_idx + m * NHID;

    float a0 = 0.0f, a1 = 0.0f, a2 = 0.0f, a3 = 0.0f;
    for (int c = 0; c < nnz; c += 128) {
        int cn = nnz - c; if (cn > 128) cn = 128;
        if (tid < cn) sidx[tid] = idx[c + tid];
        __syncthreads();
#pragma unroll 4
        for (int i = 0; i < cn; i++) {
            int k = sidx[i];
            float4 w = *(const float4*)&g_Wt[k * NOUT + n0];
            a0 = __fadd_rn(a0, w.x);
            a1 = __fadd_rn(a1, w.y);
            a2 = __fadd_rn(a2, w.z);
            a3 = __fadd_rn(a3, w.w);
        }
        __syncthreads();
    }
    float acc[4] = {a0, a1, a2, a3};
#pragma unroll
    for (int j = 0; j < 4; j++) {
        float o = __fadd_rn(acc[j], bout[n0 + j]);
        if (o > 0.0f) {
            int oi = m * NOUT + n0 + j;
            s[oi] = s[oi] + 1.0f;
        }
    }
}

// ---------------- launch ---------------------------------------------------
extern "C" void kernel_launch(void* const* d_in, const int* in_sizes, int n_in,
                              void* d_out, int out_size) {
    const float* x    = (const float*)d_in[0];
    const float* Win  = (const float*)d_in[1];
    const float* Wout = (const float*)d_in[2];
    const float* bout = (const float*)d_in[3];
    float* s = (float*)d_out;

    init_kernel<<<(NTOT + 255) / 256, 256>>>(x, s);
    transpose_wout<<<dim3(NHID / 32, NOUT / 32), 256>>>(Wout);
    for (int t = 0; t < NSTEP; t++) {
        spike_kernel<<<(NTOT + 255) / 256, 256>>>(t);
        gemm_lif<<<dim3(NHID / 64, NB / 64), 256>>>(Win);
        pack_kernel<<<NB / 8, 256>>>();
        gemm_out_sparse<<<NB, 128>>>(bout, s);
    }
}